// round 11
// baseline (speedup 1.0000x reference)
#include <cuda_runtime.h>
#include <math.h>

#define NATOM 2048
#define NTOK  512
#define CDIM  128
#define CZD   16
#define NHEADS 4
#define CHD   32
#define NBL   3
#define NHID  256
#define NQ    32
#define NKEY  128
#define NQB   (NATOM/NQ)
#define EPS   1e-5f
#define NEGBIG -1e30f
#define NC    (NATOM*CDIM)

#define COPY_CTAS (NC/256)
#define MB_CTAS   (NATOM/8)
#define PRE_CTAS  (18*64)
#define PB_CTAS   NATOM
#define T1_CTAS   (NATOM/4)      /* 512: trans1 at 4 rows/CTA */

// ---------------- scratch ----------------
__device__ float g_maskbias[NATOM];
__device__ float g_gate1[NBL*NC];
__device__ float g_shift1[NBL*NC];
__device__ float g_gate2[NBL*NC];
__device__ float g_shift2[NBL*NC];
__device__ float g_og1[NBL*NC];
__device__ float g_og2[NBL*NC];
__device__ float g_pb[NBL*NHEADS*NATOM*NKEY];
__device__ float g_a[NC];
__device__ float g_q[NC];
__device__ float g_k[NC];
__device__ float g_v[NC];
__device__ float g_g[NC];
__device__ float g_ob[NC];
__device__ float g_hidden[NATOM*NHID];

__device__ __forceinline__ float sigm(float x){ return 1.f/(1.f+expf(-x)); }

// ---------------- prep: copy_in + maskbias ----------------
__global__ void prep_kernel(const float* __restrict__ ql,
                            const float* __restrict__ a2t, const float* __restrict__ tm){
    int x = blockIdx.x, t = threadIdx.x;
    if (x < COPY_CTAS){
        int i = x*256 + t;
        g_a[i] = ql[i];
    } else {
        int w = t >> 5, l = t & 31;
        int n = (x - COPY_CTAS)*8 + w;
        const float* row = a2t + (size_t)n*NTOK;
        float s = 0.f;
        for (int i = l; i < NTOK; i += 32) s += row[i]*tm[i];
        #pragma unroll
        for (int o = 16; o; o >>= 1) s += __shfl_xor_sync(0xffffffffu, s, o);
        if (l == 0) g_maskbias[n] = (s - 1.0f)*1e9f;
    }
}

// ---------------- stage2: 18 precompute GEMMs (LN inline) UNION pair-bias ----------
__global__ void __launch_bounds__(128) stage2_kernel(
    const float* __restrict__ cl, const float* __restrict__ plm,
    const float* __restrict__ gz, const float* __restrict__ bz, const float* __restrict__ wz,
    const float* __restrict__ a1gs, const float* __restrict__ a1ws,
    const float* __restrict__ a1bs, const float* __restrict__ a1wsb,
    const float* __restrict__ a2gs, const float* __restrict__ a2ws,
    const float* __restrict__ a2bs, const float* __restrict__ a2wsb,
    const float* __restrict__ wog1, const float* __restrict__ bog1,
    const float* __restrict__ wog2, const float* __restrict__ bog2)
{
    int t = threadIdx.x;
    if (blockIdx.x < PRE_CTAS){
        int my = blockIdx.x / 64;
        int tile = blockIdx.x % 64;
        int b = my/6, m = my%6;
        size_t oW = (size_t)b*CDIM*CDIM, o1 = (size_t)b*CDIM, oC = (size_t)b*NC;
        const float* gs = 0; const float* W = 0;
        const float* bias = 0; float* out = 0; int sig = 0; int doLN = (m < 4);
        switch(m){
            case 0: gs=a1gs+o1; W=a1ws +oW; bias=a1bs+o1; sig=1; out=g_gate1 +oC; break;
            case 1: gs=a1gs+o1; W=a1wsb+oW;               sig=0; out=g_shift1+oC; break;
            case 2: gs=a2gs+o1; W=a2ws +oW; bias=a2bs+o1; sig=1; out=g_gate2 +oC; break;
            case 3: gs=a2gs+o1; W=a2wsb+oW;               sig=0; out=g_shift2+oC; break;
            case 4: W=wog1+oW; bias=bog1+o1; sig=1; out=g_og1+oC; break;
            default: W=wog2+oW; bias=bog2+o1; sig=1; out=g_og2+oC; break;
        }
        __shared__ __align__(16) float ins[32][CDIM];
        int m0 = tile*32;
        const float4* in4 = (const float4*)cl;
        for (int idx = t; idx < 32*32; idx += 128){
            int r = idx >> 5, c4 = idx & 31;
            *(float4*)&ins[r][c4*4] = in4[(size_t)(m0+r)*32 + c4];
        }
        __syncthreads();
        if (doLN){
            int w = t >> 5, l = t & 31;
            for (int r8 = 0; r8 < 8; r8++){
                int r = w*8 + r8;
                float x0=ins[r][l], x1=ins[r][l+32], x2=ins[r][l+64], x3=ins[r][l+96];
                float s = x0+x1+x2+x3;
                float s2 = x0*x0+x1*x1+x2*x2+x3*x3;
                #pragma unroll
                for (int o = 16; o; o >>= 1){
                    s  += __shfl_xor_sync(0xffffffffu, s, o);
                    s2 += __shfl_xor_sync(0xffffffffu, s2, o);
                }
                float mean = s*(1.f/CDIM);
                float var  = s2*(1.f/CDIM) - mean*mean;
                float rstd = rsqrtf(var + EPS);
                ins[r][l]    = (x0-mean)*rstd*gs[l];
                ins[r][l+32] = (x1-mean)*rstd*gs[l+32];
                ins[r][l+64] = (x2-mean)*rstd*gs[l+64];
                ins[r][l+96] = (x3-mean)*rstd*gs[l+96];
            }
            __syncthreads();
        }
        int c0 = (t & 63)*2;
        int rg = (t >> 6)*16;
        float acc0[16], acc1[16];
        #pragma unroll
        for (int i = 0; i < 16; i++){ acc0[i]=0.f; acc1[i]=0.f; }
        for (int k4 = 0; k4 < CDIM/4; k4++){
            float2 w0 = *(const float2*)&W[(k4*4+0)*CDIM + c0];
            float2 w1 = *(const float2*)&W[(k4*4+1)*CDIM + c0];
            float2 w2 = *(const float2*)&W[(k4*4+2)*CDIM + c0];
            float2 w3 = *(const float2*)&W[(k4*4+3)*CDIM + c0];
            #pragma unroll
            for (int i = 0; i < 16; i++){
                float4 a = *(const float4*)&ins[rg+i][k4*4];
                acc0[i] = fmaf(a.x, w0.x, fmaf(a.y, w1.x, fmaf(a.z, w2.x, fmaf(a.w, w3.x, acc0[i]))));
                acc1[i] = fmaf(a.x, w0.y, fmaf(a.y, w1.y, fmaf(a.z, w2.y, fmaf(a.w, w3.y, acc1[i]))));
            }
        }
        float b0 = bias ? bias[c0] : 0.f;
        float b1 = bias ? bias[c0+1] : 0.f;
        #pragma unroll
        for (int i = 0; i < 16; i++){
            float v0 = acc0[i] + b0, v1 = acc1[i] + b1;
            if (sig){ v0 = sigm(v0); v1 = sigm(v1); }
            float* o = out + (size_t)(m0+rg+i)*CDIM + c0;
            o[0] = v0; o[1] = v1;
        }
    } else {
        __shared__ float wzc[CZD][12];
        __shared__ float bzd[12];
        for (int idx = t; idx < CZD*12; idx += 128){
            int c = idx/12, id = idx%12, b = id>>2, h = id&3;
            wzc[c][id] = gz[b*CZD + c]*wz[(b*CZD + c)*4 + h];
        }
        if (t < 12){
            int b = t>>2, h = t&3; float s = 0.f;
            for (int c = 0; c < CZD; c++) s += bz[b*CZD + c]*wz[(b*CZD + c)*4 + h];
            bzd[t] = s;
        }
        __syncthreads();
        int n = blockIdx.x - PRE_CTAS;
        int slot = t;
        int m = (n & ~31) - 48 + slot;
        if (m < 0 || m >= NATOM){
            #pragma unroll
            for (int idx = 0; idx < 12; idx++)
                g_pb[((size_t)idx*NATOM + n)*NKEY + slot] = NEGBIG;
            return;
        }
        const float4* p = (const float4*)(plm + ((size_t)n*NATOM + m)*CZD);
        float x[16];
        float4 f;
        f = p[0]; x[0]=f.x; x[1]=f.y; x[2]=f.z; x[3]=f.w;
        f = p[1]; x[4]=f.x; x[5]=f.y; x[6]=f.z; x[7]=f.w;
        f = p[2]; x[8]=f.x; x[9]=f.y; x[10]=f.z; x[11]=f.w;
        f = p[3]; x[12]=f.x; x[13]=f.y; x[14]=f.z; x[15]=f.w;
        float s = 0.f, s2 = 0.f;
        #pragma unroll
        for (int c = 0; c < 16; c++){ s += x[c]; s2 += x[c]*x[c]; }
        float mean = s*(1.f/16.f);
        float var  = s2*(1.f/16.f) - mean*mean;
        float rstd = rsqrtf(var + EPS);
        float val[12];
        #pragma unroll
        for (int idx = 0; idx < 12; idx++) val[idx] = 0.f;
        #pragma unroll
        for (int c = 0; c < 16; c++){
            float z = (x[c]-mean)*rstd;
            #pragma unroll
            for (int idx = 0; idx < 12; idx++) val[idx] += z*wzc[c][idx];
        }
        float mb = g_maskbias[m];
        #pragma unroll
        for (int idx = 0; idx < 12; idx++)
            g_pb[((size_t)idx*NATOM + n)*NKEY + slot] = val[idx] + bzd[idx] + mb;
    }
}

// ---------------- per-block: AdaLN + {q,k,v,g}, 256 threads ------------------------
__global__ void __launch_bounds__(256) adaln_proj_kernel(
                                  const float* __restrict__ gate1, const float* __restrict__ shift1,
                                  const float* __restrict__ wq, const float* __restrict__ bq,
                                  const float* __restrict__ wk, const float* __restrict__ wv,
                                  const float* __restrict__ wg){
    __shared__ __align__(16) float als[16][CDIM];
    int t = threadIdx.x; int m0 = blockIdx.x*16;
    int mat = blockIdx.y;
    int w = t >> 5, l = t & 31;
    for (int idx = t; idx < 16*32; idx += 256){
        int r = idx >> 5, c4 = idx & 31;
        *(float4*)&als[r][c4*4] = *(const float4*)(g_a + (size_t)(m0+r)*CDIM + c4*4);
    }
    __syncthreads();
    for (int r = 0; r < 2; r++){
        int i = w*2 + r; int n = m0 + i;
        float x0=als[i][l], x1=als[i][l+32], x2=als[i][l+64], x3=als[i][l+96];
        float s = x0+x1+x2+x3;
        float s2 = x0*x0+x1*x1+x2*x2+x3*x3;
        #pragma unroll
        for (int o = 16; o; o >>= 1){
            s  += __shfl_xor_sync(0xffffffffu, s, o);
            s2 += __shfl_xor_sync(0xffffffffu, s2, o);
        }
        float mean = s*(1.f/CDIM);
        float var  = s2*(1.f/CDIM) - mean*mean;
        float rstd = rsqrtf(var + EPS);
        float a0=(x0-mean)*rstd, a1=(x1-mean)*rstd, a2=(x2-mean)*rstd, a3=(x3-mean)*rstd;
        size_t nb = (size_t)n*CDIM;
        als[i][l]    = gate1[nb+l]   *a0 + shift1[nb+l];
        als[i][l+32] = gate1[nb+l+32]*a1 + shift1[nb+l+32];
        als[i][l+64] = gate1[nb+l+64]*a2 + shift1[nb+l+64];
        als[i][l+96] = gate1[nb+l+96]*a3 + shift1[nb+l+96];
    }
    __syncthreads();
    const float* W; float* O;
    switch(mat){
        case 0: W = wq; O = g_q; break;
        case 1: W = wk; O = g_k; break;
        case 2: W = wv; O = g_v; break;
        default: W = wg; O = g_g; break;
    }
    int col = t & 127;
    int rg = (t >> 7)*8;
    float acc[8];
    #pragma unroll
    for (int i = 0; i < 8; i++) acc[i] = 0.f;
    #pragma unroll 2
    for (int k4 = 0; k4 < CDIM/4; k4++){
        float w0 = W[(k4*4+0)*CDIM + col];
        float w1 = W[(k4*4+1)*CDIM + col];
        float w2 = W[(k4*4+2)*CDIM + col];
        float w3 = W[(k4*4+3)*CDIM + col];
        #pragma unroll
        for (int i = 0; i < 8; i++){
            float4 a = *(const float4*)&als[rg+i][k4*4];
            acc[i] = fmaf(a.x, w0, fmaf(a.y, w1, fmaf(a.z, w2, fmaf(a.w, w3, acc[i]))));
        }
    }
    float bb = (mat == 0) ? bq[col] : 0.f;
    #pragma unroll
    for (int i = 0; i < 8; i++){
        float v = acc[i] + bb;
        if (mat == 3) v = sigm(v);
        O[(size_t)(m0+rg+i)*CDIM + col] = v;
    }
}

// ---------------- union: attention (x<256) + trans1 4-row (x>=256), 256 threads ----
__global__ void __launch_bounds__(256) mid_kernel(const float* __restrict__ pb,
                           const float* __restrict__ gate2, const float* __restrict__ shift2,
                           const float* __restrict__ wt1, const float* __restrict__ wt2){
    int t = threadIdx.x;
    if (blockIdx.x < 256){
        __shared__ __align__(16) float qs[32][32];
        __shared__ __align__(16) float vs[128][32];
        __shared__ __align__(16) float buf[128*32];
        int j = blockIdx.x & 63, h = blockIdx.x >> 6;
        int n0 = j*NQ, w0 = j*NQ - 48, hd0 = h*CHD;
        for (int idx = t; idx < 32*32; idx += 256){
            int i = idx >> 5, d = idx & 31;
            qs[i][d] = g_q[(size_t)(n0+i)*CDIM + hd0 + d];
        }
        for (int idx = t; idx < 128*32; idx += 256){
            int m = idx >> 5, d = idx & 31;
            int key = w0 + m;
            float kk = 0.f, vv = 0.f;
            if (key >= 0 && key < NATOM){
                kk = g_k[(size_t)key*CDIM + hd0 + d];
                vv = g_v[(size_t)key*CDIM + hd0 + d];
            }
            buf[m*32 + d] = kk; vs[m][d] = vv;
        }
        __syncthreads();
        int key = t & 127, qh = t >> 7;
        float kr[32];
        #pragma unroll
        for (int d = 0; d < 32; d++) kr[d] = buf[key*32 + d];
        __syncthreads();
        const float scale = 0.17677669529663687f;
        const float* pbr = pb + (size_t)h*NATOM*NKEY + (size_t)n0*NKEY;
        #pragma unroll 4
        for (int i2 = 0; i2 < 16; i2++){
            int i = qh*16 + i2;
            float acc = 0.f;
            #pragma unroll
            for (int d4 = 0; d4 < 8; d4++){
                float4 q = *(const float4*)&qs[i][d4*4];
                acc = fmaf(q.x, kr[d4*4+0], fmaf(q.y, kr[d4*4+1],
                      fmaf(q.z, kr[d4*4+2], fmaf(q.w, kr[d4*4+3], acc))));
            }
            buf[i*128 + key] = acc*scale + pbr[i*NKEY + key];
        }
        __syncthreads();
        int w = t >> 5, l = t & 31;
        for (int r = 0; r < 4; r++){
            int i = w*4 + r;
            float x0=buf[i*128+l], x1=buf[i*128+l+32], x2=buf[i*128+l+64], x3=buf[i*128+l+96];
            float mx = fmaxf(fmaxf(x0,x1), fmaxf(x2,x3));
            #pragma unroll
            for (int o = 16; o; o >>= 1) mx = fmaxf(mx, __shfl_xor_sync(0xffffffffu, mx, o));
            float e0=expf(x0-mx), e1=expf(x1-mx), e2=expf(x2-mx), e3=expf(x3-mx);
            float s = e0+e1+e2+e3;
            #pragma unroll
            for (int o = 16; o; o >>= 1) s += __shfl_xor_sync(0xffffffffu, s, o);
            float inv = 1.f/s;
            buf[i*128+l]=e0*inv; buf[i*128+l+32]=e1*inv; buf[i*128+l+64]=e2*inv; buf[i*128+l+96]=e3*inv;
        }
        __syncthreads();
        int i = t >> 3, d0 = (t & 7)*4;
        float acc[4] = {0.f,0.f,0.f,0.f};
        #pragma unroll 2
        for (int k4 = 0; k4 < 32; k4++){              // 128 keys, 4 at a time
            float4 wg4 = *(const float4*)&buf[i*128 + k4*4];
            float4 v0 = *(const float4*)&vs[k4*4+0][d0];
            float4 v1 = *(const float4*)&vs[k4*4+1][d0];
            float4 v2 = *(const float4*)&vs[k4*4+2][d0];
            float4 v3 = *(const float4*)&vs[k4*4+3][d0];
            acc[0] = fmaf(wg4.x, v0.x, fmaf(wg4.y, v1.x, fmaf(wg4.z, v2.x, fmaf(wg4.w, v3.x, acc[0]))));
            acc[1] = fmaf(wg4.x, v0.y, fmaf(wg4.y, v1.y, fmaf(wg4.z, v2.y, fmaf(wg4.w, v3.y, acc[1]))));
            acc[2] = fmaf(wg4.x, v0.z, fmaf(wg4.y, v1.z, fmaf(wg4.z, v2.z, fmaf(wg4.w, v3.z, acc[2]))));
            acc[3] = fmaf(wg4.x, v0.w, fmaf(wg4.y, v1.w, fmaf(wg4.z, v2.w, fmaf(wg4.w, v3.w, acc[3]))));
        }
        int n = n0 + i;
        #pragma unroll
        for (int dd = 0; dd < 4; dd++){
            int c = hd0 + d0 + dd;
            g_ob[(size_t)n*CDIM + c] = g_g[(size_t)n*CDIM + c]*acc[dd];
        }
    } else {
        // ---- trans1: 4 rows/CTA ----
        __shared__ __align__(16) float a2s[4][CDIM];
        int m0 = (blockIdx.x - 256)*4;
        int w = t >> 5, l = t & 31;
        if (t < 128){
            int r = t >> 5, c4 = t & 31;
            *(float4*)&a2s[r][c4*4] = *(const float4*)(g_a + (size_t)(m0+r)*CDIM + c4*4);
        }
        __syncthreads();
        if (w < 4){
            int i = w; int n = m0 + i;
            float x0=a2s[i][l], x1=a2s[i][l+32], x2=a2s[i][l+64], x3=a2s[i][l+96];
            float s = x0+x1+x2+x3;
            float s2 = x0*x0+x1*x1+x2*x2+x3*x3;
            #pragma unroll
            for (int o = 16; o; o >>= 1){
                s  += __shfl_xor_sync(0xffffffffu, s, o);
                s2 += __shfl_xor_sync(0xffffffffu, s2, o);
            }
            float mean = s*(1.f/CDIM);
            float var  = s2*(1.f/CDIM) - mean*mean;
            float rstd = rsqrtf(var + EPS);
            size_t nb = (size_t)n*CDIM;
            a2s[i][l]    = gate2[nb+l]   *((x0-mean)*rstd) + shift2[nb+l];
            a2s[i][l+32] = gate2[nb+l+32]*((x1-mean)*rstd) + shift2[nb+l+32];
            a2s[i][l+64] = gate2[nb+l+64]*((x2-mean)*rstd) + shift2[nb+l+64];
            a2s[i][l+96] = gate2[nb+l+96]*((x3-mean)*rstd) + shift2[nb+l+96];
        }
        __syncthreads();
        int c = t;
        float a1[4], a2r[4];
        #pragma unroll
        for (int i = 0; i < 4; i++){ a1[i]=0.f; a2r[i]=0.f; }
        #pragma unroll 2
        for (int k4 = 0; k4 < CDIM/4; k4++){
            float w10 = wt1[(k4*4+0)*NHID + c], w20 = wt2[(k4*4+0)*NHID + c];
            float w11 = wt1[(k4*4+1)*NHID + c], w21 = wt2[(k4*4+1)*NHID + c];
            float w12 = wt1[(k4*4+2)*NHID + c], w22 = wt2[(k4*4+2)*NHID + c];
            float w13 = wt1[(k4*4+3)*NHID + c], w23 = wt2[(k4*4+3)*NHID + c];
            #pragma unroll
            for (int i = 0; i < 4; i++){
                float4 a = *(const float4*)&a2s[i][k4*4];
                a1[i]  = fmaf(a.x, w10, fmaf(a.y, w11, fmaf(a.z, w12, fmaf(a.w, w13, a1[i]))));
                a2r[i] = fmaf(a.x, w20, fmaf(a.y, w21, fmaf(a.z, w22, fmaf(a.w, w23, a2r[i]))));
            }
        }
        #pragma unroll
        for (int i = 0; i < 4; i++){
            float h1 = a1[i];
            g_hidden[(size_t)(m0+i)*NHID + c] = h1*sigm(h1)*a2r[i];
        }
    }
}

// ---------------- light tail: 4 rows, 512 CTAs -> outp ----------------------------
__global__ void __launch_bounds__(256) tail_kernel(
                            const float* __restrict__ wo, const float* __restrict__ og1,
                            const float* __restrict__ wt3, const float* __restrict__ og2,
                            float* __restrict__ outp){
    __shared__ __align__(16) float obs[4][CDIM];
    __shared__ __align__(16) float hid[4][NHID];
    int t = threadIdx.x;
    int m0 = blockIdx.x*4;
    if (t < 128){
        int r = t >> 5, c4 = t & 31;
        *(float4*)&obs[r][c4*4] = *(const float4*)(g_ob + (size_t)(m0+r)*CDIM + c4*4);
    }
    {
        int r = t >> 6, c4 = t & 63;
        *(float4*)&hid[r][c4*4] = *(const float4*)(g_hidden + (size_t)(m0+r)*NHID + c4*4);
    }
    __syncthreads();
    int col = t & 127, half = t >> 7;
    int r0 = half*2;
    float attr[2];
    {
        float acc[2] = {0.f,0.f};
        #pragma unroll 2
        for (int k4 = 0; k4 < CDIM/4; k4++){
            float w0 = wo[(k4*4+0)*CDIM + col];
            float w1 = wo[(k4*4+1)*CDIM + col];
            float w2 = wo[(k4*4+2)*CDIM + col];
            float w3 = wo[(k4*4+3)*CDIM + col];
            #pragma unroll
            for (int i = 0; i < 2; i++){
                float4 a = *(const float4*)&obs[r0+i][k4*4];
                acc[i] = fmaf(a.x, w0, fmaf(a.y, w1, fmaf(a.z, w2, fmaf(a.w, w3, acc[i]))));
            }
        }
        size_t ob = (size_t)(m0+r0)*CDIM + col;
        attr[0] = og1[ob       ]*acc[0];
        attr[1] = og1[ob + CDIM]*acc[1];
    }
    {
        float acc[2] = {0.f,0.f};
        #pragma unroll 2
        for (int k4 = 0; k4 < NHID/4; k4++){
            float w0 = wt3[(k4*4+0)*CDIM + col];
            float w1 = wt3[(k4*4+1)*CDIM + col];
            float w2 = wt3[(k4*4+2)*CDIM + col];
            float w3 = wt3[(k4*4+3)*CDIM + col];
            #pragma unroll
            for (int i = 0; i < 2; i++){
                float4 a = *(const float4*)&hid[r0+i][k4*4];
                acc[i] = fmaf(a.x, w0, fmaf(a.y, w1, fmaf(a.z, w2, fmaf(a.w, w3, acc[i]))));
            }
        }
        size_t ob = (size_t)(m0+r0)*CDIM + col;
        outp[ob       ] = attr[0] + og2[ob       ]*acc[0];
        outp[ob + CDIM] = attr[1] + og2[ob + CDIM]*acc[1];
    }
}

// ---------------- host launcher ----------------
extern "C" void kernel_launch(void* const* d_in, const int* in_sizes, int n_in,
                              void* d_out, int out_size){
    const float* ql       = (const float*)d_in[0];
    const float* cl       = (const float*)d_in[1];
    const float* plm      = (const float*)d_in[2];
    const float* a2t      = (const float*)d_in[3];
    const float* tm       = (const float*)d_in[4];
    const float* ada1_gs  = (const float*)d_in[5];
    const float* ada1_ws  = (const float*)d_in[6];
    const float* ada1_bs  = (const float*)d_in[7];
    const float* ada1_wsb = (const float*)d_in[8];
    const float* wq       = (const float*)d_in[9];
    const float* bq       = (const float*)d_in[10];
    const float* wk       = (const float*)d_in[11];
    const float* wv       = (const float*)d_in[12];
    const float* gz       = (const float*)d_in[13];
    const float* bz       = (const float*)d_in[14];
    const float* wz       = (const float*)d_in[15];
    const float* wg       = (const float*)d_in[16];
    const float* wo       = (const float*)d_in[17];
    const float* wog1     = (const float*)d_in[18];
    const float* bog1     = (const float*)d_in[19];
    const float* ada2_gs  = (const float*)d_in[20];
    const float* ada2_ws  = (const float*)d_in[21];
    const float* ada2_bs  = (const float*)d_in[22];
    const float* ada2_wsb = (const float*)d_in[23];
    const float* wt1      = (const float*)d_in[24];
    const float* wt2      = (const float*)d_in[25];
    const float* wt3      = (const float*)d_in[26];
    const float* wog2     = (const float*)d_in[27];
    const float* bog2     = (const float*)d_in[28];

    float *p_gate1, *p_shift1, *p_gate2, *p_shift2, *p_og1, *p_og2, *p_pb, *p_a;
    cudaGetSymbolAddress((void**)&p_gate1,  g_gate1);
    cudaGetSymbolAddress((void**)&p_shift1, g_shift1);
    cudaGetSymbolAddress((void**)&p_gate2,  g_gate2);
    cudaGetSymbolAddress((void**)&p_shift2, g_shift2);
    cudaGetSymbolAddress((void**)&p_og1,    g_og1);
    cudaGetSymbolAddress((void**)&p_og2,    g_og2);
    cudaGetSymbolAddress((void**)&p_pb,     g_pb);
    cudaGetSymbolAddress((void**)&p_a,      g_a);

    prep_kernel<<<COPY_CTAS + MB_CTAS, 256>>>(ql, a2t, tm);

    stage2_kernel<<<PRE_CTAS + PB_CTAS, 128>>>(cl, plm, gz, bz, wz,
        ada1_gs, ada1_ws, ada1_bs, ada1_wsb,
        ada2_gs, ada2_ws, ada2_bs, ada2_wsb,
        wog1, bog1, wog2, bog2);

    for (int b = 0; b < NBL; b++){
        size_t oC = (size_t)b*NC, oW = (size_t)b*CDIM*CDIM;
        dim3 qg(NATOM/16, 4);
        adaln_proj_kernel<<<qg, 256>>>(p_gate1+oC, p_shift1+oC,
                                       wq+oW, bq+(size_t)b*CDIM, wk+oW, wv+oW, wg+oW);
        mid_kernel<<<256 + T1_CTAS, 256>>>(p_pb + (size_t)b*NHEADS*NATOM*NKEY,
                                           p_gate2+oC, p_shift2+oC,
                                           wt1+(size_t)b*CDIM*NHID, wt2+(size_t)b*CDIM*NHID);
        float* outp = (b == NBL-1) ? (float*)d_out : p_a;
        tail_kernel<<<NATOM/4, 256>>>(wo+oW, p_og1+oC,
                                      wt3+(size_t)b*NHID*CDIM, p_og2+oC, outp);
    }
}